// round 16
// baseline (speedup 1.0000x reference)
#include <cuda_runtime.h>
#include <cuda_bf16.h>
#include <math.h>

// GGNN + Set2Set. R13: step kernel with conflict-free 16B-slice gather,
// cp.async staging (h, esrc, etype W tiles) overlapped with gather,
// h fp32 pitch 256 + HP-pair overlay. mma skeleton from R8 unchanged.

#define NPG 200
#define EPG 3200
#define NET 6
#define NGR 320
#define NTH 448

// ---- step kernel SMEM layout (bytes) ----
#define H_F32 0              // 200 rows x 256B fp32 h (contiguous rows)
#define SP_HI 51200          // 112 rows x 128B (s/a hi)
#define SP_LO 65536
#define WB    79872          // 16384B staged B fragments
#define ESRCB 96256          // 3200B
#define OFFLB 99456          // 606 u16 (pad 1216)
#define ST_SMEM 100672
// HP pair (own half bf16 hi/lo) overlays H_F32 after etype phase:
//   half==0 -> hpb = 25600 (own fp32 rows live at [0,25600))
//   half==1 -> hpb = 0     (own fp32 rows live at [25600,51200))
// HP_LO = hpb + 12800. ldmatrix rows >=100 read garbage (discarded).

// ---------------- global scratch ----------------
__device__ float g_hA[64000 * 64];
__device__ float g_hB[64000 * 64];
__device__ unsigned char  g_esrc[NGR * EPG];
__device__ unsigned short g_off[NGR * 1216];
// B fragments: [tile][ (ntg*4+ks)*32 + lane ] = uint4 {hi_r0, hi_r1, lo_r0, lo_r1}
__device__ unsigned int g_wfrag[12 * 4096];
// set2set state
__device__ float g_qstar[NGR * 128];
__device__ float g_lh[3 * NGR * 64];
__device__ float g_lc[3 * NGR * 64];
__device__ float g_q[NGR * 64];
__device__ float g_wtl[114688];
__device__ float g_bsum[768];

__device__ __forceinline__ float sigf(float x) { return 1.0f / (1.0f + __expf(-x)); }
__device__ __forceinline__ float tanhfast(float x) {
    x = fminf(fmaxf(x, -15.0f), 15.0f);
    float e = __expf(2.0f * x);
    return (e - 1.0f) / (e + 1.0f);
}
__device__ __forceinline__ float blo(unsigned w) { return __uint_as_float(w << 16); }
__device__ __forceinline__ float bhi(unsigned w) { return __uint_as_float(w & 0xffff0000u); }
__device__ __forceinline__ void cvtpair(float a, float b, unsigned& hi, unsigned& lo) {
    asm("cvt.rn.bf16x2.f32 %0, %1, %2;" : "=r"(hi) : "f"(b), "f"(a));
    float fa = blo(hi), fb = bhi(hi);
    asm("cvt.rn.bf16x2.f32 %0, %1, %2;" : "=r"(lo) : "f"(b - fb), "f"(a - fa));
}
__device__ __forceinline__ unsigned smem_u32(const void* p) {
    unsigned a;
    asm("{ .reg .u64 t; cvta.to.shared.u64 t, %1; cvt.u32.u64 %0, t; }" : "=r"(a) : "l"(p));
    return a;
}
__device__ __forceinline__ void ldmA(unsigned addr, unsigned r[4]) {
    asm volatile("ldmatrix.sync.aligned.m8n8.x4.shared.b16 {%0,%1,%2,%3}, [%4];"
                 : "=r"(r[0]), "=r"(r[1]), "=r"(r[2]), "=r"(r[3]) : "r"(addr));
}
__device__ __forceinline__ void mma16816(float* c, const unsigned a[4], unsigned b0, unsigned b1) {
    asm volatile("mma.sync.aligned.m16n8k16.row.col.f32.bf16.bf16.f32 "
                 "{%0,%1,%2,%3}, {%4,%5,%6,%7}, {%8,%9}, {%0,%1,%2,%3};"
                 : "+f"(c[0]), "+f"(c[1]), "+f"(c[2]), "+f"(c[3])
                 : "r"(a[0]), "r"(a[1]), "r"(a[2]), "r"(a[3]), "r"(b0), "r"(b1));
}
__device__ __forceinline__ void cp16(unsigned dst, const void* src) {
    asm volatile("cp.async.ca.shared.global [%0], [%1], 16;" :: "r"(dst), "l"(src) : "memory");
}
#define CP_COMMIT() asm volatile("cp.async.commit_group;" ::: "memory")
#define CP_WAIT0()  asm volatile("cp.async.wait_group 0;" ::: "memory")

// ---------------- prep: bake packed B fragments (unchanged layout) ----------------
__global__ void prep_kernel(const float* __restrict__ W_edge,
                            const float* __restrict__ gWih,
                            const float* __restrict__ gWhh) {
    int i = blockIdx.x * blockDim.x + threadIdx.x;
    if (i >= 49152) return;
    int word = i & 3, lane = (i >> 2) & 31, ks = (i >> 7) & 3;
    int ntg = (i >> 9) & 7, tile = i >> 12;
    int reg = word & 1, split = word >> 1;
    int n = ntg * 8 + (lane >> 2);
    int k = ks * 16 + (lane & 3) * 2 + reg * 8;
    float w0, w1;
    if (tile < 6) {
        w0 = W_edge[(tile * 64 + k) * 64 + n];
        w1 = W_edge[(tile * 64 + k + 1) * 64 + n];
    } else {
        int p = tile - 6;
        const int g0s[6] = { 0, 0, 128, 128, 64, 64 };
        const float* M = (p == 0 || p == 3 || p == 4) ? gWih : gWhh;
        w0 = M[(g0s[p] + n) * 64 + k];
        w1 = M[(g0s[p] + n) * 64 + k + 1];
    }
    unsigned hw, lw;
    cvtpair(w0, w1, hw, lw);
    g_wfrag[tile * 4096 + (((ntg * 4 + ks) * 32 + lane) << 2) + word] = split ? lw : hw;
}

// ---------------- prep: lstm weights + bias sums + state init ----------------
__global__ void prep_lstm(const float* __restrict__ wih0, const float* __restrict__ whh0,
                          const float* __restrict__ bih0, const float* __restrict__ bhh0,
                          const float* __restrict__ wih1, const float* __restrict__ whh1,
                          const float* __restrict__ bih1, const float* __restrict__ bhh1,
                          const float* __restrict__ wih2, const float* __restrict__ whh2,
                          const float* __restrict__ bih2, const float* __restrict__ bhh2) {
    int i = blockIdx.x * blockDim.x + threadIdx.x;
    if (i < 114688) {
        const int   bases[6]  = { 0, 32768, 49152, 65536, 81920, 98304 };
        const int   indims[6] = { 128, 64, 64, 64, 64, 64 };
        const float* Ws[6] = { wih0, whh0, wih1, whh1, wih2, whh2 };
        int seg = 5;
#pragma unroll
        for (int s = 0; s < 5; s++) if (i < bases[s + 1]) { seg = s; break; }
        int idx = i - bases[seg];
        int k4 = idx >> 10, r = idx & 1023, t = r >> 2, kk = r & 3;
        g_wtl[i] = Ws[seg][t * indims[seg] + k4 * 4 + kk];
    } else if (i < 115456) {
        int i2 = i - 114688;
        int l = i2 >> 8, t = i2 & 255;
        const float* bi = (l == 0) ? bih0 : (l == 1) ? bih1 : bih2;
        const float* bh = (l == 0) ? bhh0 : (l == 1) ? bhh1 : bhh2;
        g_bsum[i2] = bi[t] + bh[t];
    }
    if (i < NGR * 128) g_qstar[i] = 0.0f;
    if (i < 3 * NGR * 64) { g_lh[i] = 0.0f; g_lc[i] = 0.0f; }
}

// ---------------- sort ----------------
__global__ __launch_bounds__(640) void sort_kernel(
    const int* __restrict__ g_src, const int* __restrict__ g_dst,
    const int* __restrict__ g_ety) {
    __shared__ int cnt[1280];
    __shared__ int csum[256];
    const int tid = threadIdx.x;
    const int g = blockIdx.x;
    const int nbase = g * NPG, ebase = g * EPG;
    for (int i = tid; i < 1280; i += 640) cnt[i] = 0;
    __syncthreads();
    for (int e = tid; e < EPG; e += 640) {
        int key = g_ety[ebase + e] * NPG + (g_dst[ebase + e] - nbase);
        atomicAdd(&cnt[key], 1);
    }
    __syncthreads();
    if (tid < 256) {
        int s = 0;
#pragma unroll
        for (int j = 0; j < 5; j++) s += cnt[tid * 5 + j];
        csum[tid] = s;
    }
    __syncthreads();
    if (tid < 32) {
        int s = 0;
#pragma unroll
        for (int j = 0; j < 8; j++) s += csum[tid * 8 + j];
        int v = s;
        for (int o = 1; o < 32; o <<= 1) {
            int u = __shfl_up_sync(0xffffffffu, v, o);
            if (tid >= o) v += u;
        }
        int run = v - s;
#pragma unroll
        for (int j = 0; j < 8; j++) {
            int c = csum[tid * 8 + j];
            csum[tid * 8 + j] = run;
            run += c;
        }
    }
    __syncthreads();
    if (tid < 256) {
        int run = csum[tid];
#pragma unroll
        for (int j = 0; j < 5; j++) {
            int idx = tid * 5 + j;
            int c = cnt[idx];
            if (idx < 1216) g_off[g * 1216 + idx] = (unsigned short)run;
            run += c;
        }
    }
    __syncthreads();
    if (tid < 256) {
        int run = csum[tid];
#pragma unroll
        for (int j = 0; j < 5; j++) {
            int idx = tid * 5 + j;
            int c = cnt[idx];
            cnt[idx] = run;
            run += c;
        }
    }
    __syncthreads();
    for (int e = tid; e < EPG; e += 640) {
        int key = g_ety[ebase + e] * NPG + (g_dst[ebase + e] - nbase);
        int pos = atomicAdd(&cnt[key], 1);
        g_esrc[g * EPG + pos] = (unsigned char)(g_src[ebase + e] - nbase);
    }
}

// ---------------- step kernel ----------------
__global__ __launch_bounds__(NTH, 2) void step_kernel(
    const float* __restrict__ feats,
    const float* __restrict__ b_edge,
    const float* __restrict__ gbih,
    const float* __restrict__ gbhh,
    int step) {
    extern __shared__ char sm[];
    unsigned smb = smem_u32(sm);
    unsigned char* esrc = (unsigned char*)(sm + ESRCB);
    unsigned short* offl = (unsigned short*)(sm + OFFLB);

    const int tid = threadIdx.x;
    const int g = blockIdx.x >> 1;
    const int half = blockIdx.x & 1;
    const int lane = tid & 31;
    const int wid = tid >> 5;
    const int mt = wid >> 1;
    const int nh = wid & 1;
    const int lrow = mt * 16 + (lane & 15);
    const int lmt = lane >> 4;
    const int g8 = lane >> 2, q = lane & 3;
    const int r1l = mt * 16 + g8, r2l = r1l + 8;
    const int hpb = half ? 0 : 25600;      // HP pair base (overlay on H_F32)

    const float* hsrc = (step == 0) ? feats : ((step & 1) ? g_hA : g_hB);
    float* hdst = (step & 1) ? g_hB : g_hA;

    // ---- async staging: h (contiguous 51200B), W tile 0, esrc ----
    {
        const char* hg = (const char*)(hsrc + (size_t)g * NPG * 64);
        for (int i = tid; i < 3200; i += NTH) cp16(smb + H_F32 + i * 16, hg + i * 16);
        const char* w0 = (const char*)g_wfrag;
        for (int i = tid; i < 1024; i += NTH) cp16(smb + WB + i * 16, w0 + i * 16);
        const char* es = (const char*)(g_esrc + g * EPG);
        for (int i = tid; i < 200; i += NTH) cp16(smb + ESRCB + i * 16, es + i * 16);
        CP_COMMIT();
    }
    for (int j = tid; j < 606; j += NTH) {
        int t = j / 101, i2 = j % 101;
        offl[j] = g_off[g * 1216 + t * 200 + half * 100 + i2];
    }
    CP_WAIT0();
    __syncthreads();

    // ---- etype passes: aC = sum_t (S_t @ W_t) ----
    float aC[16];
#pragma unroll
    for (int i = 0; i < 16; i++) aC[i] = 0.0f;

    for (int t = 0; t < NET; t++) {
        if (t > 0) {
            __syncthreads();   // mma_{t-1} done reading WB + SP
            const char* wt = (const char*)(g_wfrag + t * 4096);
            for (int i = tid; i < 1024; i += NTH) cp16(smb + WB + i * 16, wt + i * 16);
            CP_COMMIT();
        }
        // gather: 16B-slice items (conflict-free quarter-warp phases), edge unroll x2
        for (int i = tid; i < 1600; i += NTH) {
            int n = i >> 4, s = i & 15;
            int b = t * 101 + n;
            int j0 = offl[b], j1 = offl[b + 1];
            float4 acc = make_float4(0.f, 0.f, 0.f, 0.f);
            float4 acc2 = make_float4(0.f, 0.f, 0.f, 0.f);
            int j = j0;
            for (; j + 1 < j1; j += 2) {
                float4 va = *(const float4*)(sm + H_F32 + (int)esrc[j] * 256 + s * 16);
                float4 vb = *(const float4*)(sm + H_F32 + (int)esrc[j + 1] * 256 + s * 16);
                acc.x += va.x;  acc.y += va.y;  acc.z += va.z;  acc.w += va.w;
                acc2.x += vb.x; acc2.y += vb.y; acc2.z += vb.z; acc2.w += vb.w;
            }
            if (j < j1) {
                float4 va = *(const float4*)(sm + H_F32 + (int)esrc[j] * 256 + s * 16);
                acc.x += va.x; acc.y += va.y; acc.z += va.z; acc.w += va.w;
            }
            acc.x += acc2.x; acc.y += acc2.y; acc.z += acc2.z; acc.w += acc2.w;
            unsigned hw0, lw0, hw1, lw1;
            cvtpair(acc.x, acc.y, hw0, lw0);
            cvtpair(acc.z, acc.w, hw1, lw1);
            int off = n * 128 + ((((s >> 1) + n) & 7) << 4) + (s & 1) * 8;
            *(uint2*)(sm + SP_HI + off) = make_uint2(hw0, hw1);
            *(uint2*)(sm + SP_LO + off) = make_uint2(lw0, lw1);
        }
        if (t > 0) CP_WAIT0();
        __syncthreads();
#pragma unroll
        for (int ks = 0; ks < 4; ks++) {
            int unit = 2 * ks + lmt;
            unsigned ah[4], al[4];
            ldmA(smb + SP_HI + lrow * 128 + (((unit + lrow) & 7) << 4), ah);
            ldmA(smb + SP_LO + lrow * 128 + (((unit + lrow) & 7) << 4), al);
#pragma unroll
            for (int nt = 0; nt < 4; nt++) {
                int ntg = nh * 4 + nt;
                uint4 bb = *(const uint4*)(sm + WB + (((ntg * 4 + ks) * 32 + lane) << 4));
                mma16816(aC + nt * 4, al, bb.x, bb.y);
                mma16816(aC + nt * 4, ah, bb.z, bb.w);
                mma16816(aC + nt * 4, ah, bb.x, bb.y);
            }
        }
    }
    // bias: aC += cnt_t(row) * b_edge[t][col]
#pragma unroll
    for (int t = 0; t < NET; t++) {
        float c1 = (r1l < 100) ? (float)(offl[t * 101 + r1l + 1] - offl[t * 101 + r1l]) : 0.0f;
        float c2 = (r2l < 100) ? (float)(offl[t * 101 + r2l + 1] - offl[t * 101 + r2l]) : 0.0f;
#pragma unroll
        for (int nt = 0; nt < 4; nt++) {
            int col = nh * 32 + nt * 8 + q * 2;
            float2 b = *(const float2*)(b_edge + t * 64 + col);
            aC[nt * 4 + 0] = fmaf(c1, b.x, aC[nt * 4 + 0]);
            aC[nt * 4 + 1] = fmaf(c1, b.y, aC[nt * 4 + 1]);
            aC[nt * 4 + 2] = fmaf(c2, b.x, aC[nt * 4 + 2]);
            aC[nt * 4 + 3] = fmaf(c2, b.y, aC[nt * 4 + 3]);
        }
    }
    __syncthreads();   // all mma reads of SP + gathers of H done
    // write a -> SP bf16 pair
#pragma unroll
    for (int nt = 0; nt < 4; nt++) {
        int col = nh * 32 + nt * 8 + q * 2;
        int u = col >> 3;
        unsigned hw, lw;
        cvtpair(aC[nt * 4 + 0], aC[nt * 4 + 1], hw, lw);
        int bo1 = r1l * 128 + (((u + r1l) & 7) << 4) + q * 4;
        *(unsigned*)(sm + SP_HI + bo1) = hw;
        *(unsigned*)(sm + SP_LO + bo1) = lw;
        cvtpair(aC[nt * 4 + 2], aC[nt * 4 + 3], hw, lw);
        int bo2 = r2l * 128 + (((u + r2l) & 7) << 4) + q * 4;
        *(unsigned*)(sm + SP_HI + bo2) = hw;
        *(unsigned*)(sm + SP_LO + bo2) = lw;
    }
    // build HP pair (own half) from fp32 h into overlay region (16B slices)
    for (int i = tid; i < 1600; i += NTH) {
        int r = i >> 4, s = i & 15;
        float4 v = *(const float4*)(sm + H_F32 + (half * 100 + r) * 256 + s * 16);
        unsigned hw0, lw0, hw1, lw1;
        cvtpair(v.x, v.y, hw0, lw0);
        cvtpair(v.z, v.w, hw1, lw1);
        int off = r * 128 + ((((s >> 1) + r) & 7) << 4) + (s & 1) * 8;
        *(uint2*)(sm + hpb + off) = make_uint2(hw0, hw1);
        *(uint2*)(sm + hpb + 12800 + off) = make_uint2(lw0, lw1);
    }

    // ---- GRU ----
#define STAGEW(T) do { \
        const uint4* ws_ = (const uint4*)g_wfrag + (T) * 1024; \
        uint4 s0 = ws_[tid], s1 = ws_[tid + 448], s2; \
        if (tid < 128) s2 = ws_[tid + 896]; \
        __syncthreads(); \
        ((uint4*)(sm + WB))[tid] = s0; \
        ((uint4*)(sm + WB))[tid + 448] = s1; \
        if (tid < 128) ((uint4*)(sm + WB))[tid + 896] = s2; \
        __syncthreads(); \
    } while (0)

#define MMPASS(BASE_HI, BASE_LO, ROW, C) do { \
        _Pragma("unroll") \
        for (int ks = 0; ks < 4; ks++) { \
            int unit = 2 * ks + lmt; \
            unsigned ah[4], al[4]; \
            ldmA(smb + (BASE_HI) + (ROW) * 128 + (((unit + (ROW)) & 7) << 4), ah); \
            ldmA(smb + (BASE_LO) + (ROW) * 128 + (((unit + (ROW)) & 7) << 4), al); \
            _Pragma("unroll") \
            for (int nt = 0; nt < 4; nt++) { \
                int ntg = nh * 4 + nt; \
                uint4 bb = *(const uint4*)(sm + WB + (((ntg * 4 + ks) * 32 + lane) << 4)); \
                mma16816((C) + nt * 4, al, bb.x, bb.y); \
                mma16816((C) + nt * 4, ah, bb.z, bb.w); \
                mma16816((C) + nt * 4, ah, bb.x, bb.y); \
            } \
        } \
    } while (0)

    float C[16], rg[16];
    // r = sigmoid(a@Wih_r + h@Whh_r + b)
#pragma unroll
    for (int i = 0; i < 16; i++) C[i] = 0.0f;
    STAGEW(6);  MMPASS(SP_HI, SP_LO, lrow, C);
    STAGEW(7);  MMPASS(hpb, hpb + 12800, lrow, C);
#pragma unroll
    for (int nt = 0; nt < 4; nt++) {
        int col = nh * 32 + nt * 8 + q * 2;
        float2 bi = *(const float2*)(gbih + col);
        float2 bh = *(const float2*)(gbhh + col);
        rg[nt * 4 + 0] = sigf(C[nt * 4 + 0] + bi.x + bh.x);
        rg[nt * 4 + 1] = sigf(C[nt * 4 + 1] + bi.y + bh.y);
        rg[nt * 4 + 2] = sigf(C[nt * 4 + 2] + bi.x + bh.x);
        rg[nt * 4 + 3] = sigf(C[nt * 4 + 3] + bi.y + bh.y);
    }
    // t = r * (h@Whh_n + bhh_n)
#pragma unroll
    for (int i = 0; i < 16; i++) C[i] = 0.0f;
    STAGEW(8);  MMPASS(hpb, hpb + 12800, lrow, C);
#pragma unroll
    for (int nt = 0; nt < 4; nt++) {
        int col = nh * 32 + nt * 8 + q * 2;
        float2 bh = *(const float2*)(gbhh + 128 + col);
        rg[nt * 4 + 0] *= (C[nt * 4 + 0] + bh.x);
        rg[nt * 4 + 1] *= (C[nt * 4 + 1] + bh.y);
        rg[nt * 4 + 2] *= (C[nt * 4 + 2] + bh.x);
        rg[nt * 4 + 3] *= (C[nt * 4 + 3] + bh.y);
    }
    // n = tanh(a@Wih_n + bih_n + t)
#pragma unroll
    for (int i = 0; i < 16; i++) C[i] = 0.0f;
    STAGEW(9);  MMPASS(SP_HI, SP_LO, lrow, C);
#pragma unroll
    for (int nt = 0; nt < 4; nt++) {
        int col = nh * 32 + nt * 8 + q * 2;
        float2 bi = *(const float2*)(gbih + 128 + col);
        rg[nt * 4 + 0] = tanhfast(C[nt * 4 + 0] + bi.x + rg[nt * 4 + 0]);
        rg[nt * 4 + 1] = tanhfast(C[nt * 4 + 1] + bi.y + rg[nt * 4 + 1]);
        rg[nt * 4 + 2] = tanhfast(C[nt * 4 + 2] + bi.x + rg[nt * 4 + 2]);
        rg[nt * 4 + 3] = tanhfast(C[nt * 4 + 3] + bi.y + rg[nt * 4 + 3]);
    }
    // z = sigmoid(a@Wih_z + h@Whh_z + b); h' = n + z*(h - n)
#pragma unroll
    for (int i = 0; i < 16; i++) C[i] = 0.0f;
    STAGEW(10); MMPASS(SP_HI, SP_LO, lrow, C);
    STAGEW(11); MMPASS(hpb, hpb + 12800, lrow, C);
#pragma unroll
    for (int nt = 0; nt < 4; nt++) {
        int col = nh * 32 + nt * 8 + q * 2;
        int u = col >> 3;
        float2 bi = *(const float2*)(gbih + 64 + col);
        float2 bh2 = *(const float2*)(gbhh + 64 + col);
        if (r1l < 100) {
            int bo = r1l * 128 + (((u + r1l) & 7) << 4) + q * 4;
            unsigned hw = *(const unsigned*)(sm + hpb + bo);
            unsigned lw = *(const unsigned*)(sm + hpb + 12800 + bo);
            float h0 = blo(hw) + blo(lw), h1 = bhi(hw) + bhi(lw);
            float z0 = sigf(C[nt * 4 + 0] + bi.x + bh2.x);
            float z1 = sigf(C[nt * 4 + 1] + bi.y + bh2.y);
            float n0 = rg[nt * 4 + 0], n1 = rg[nt * 4 + 1];
            float2 o;
            o.x = fmaf(z0, h0 - n0, n0);
            o.y = fmaf(z1, h1 - n1, n1);
            *(float2*)(hdst + (g * NPG + half * 100 + r1l) * 64 + col) = o;
        }
        if (r2l < 100) {
            int bo = r2l * 128 + (((u + r2l) & 7) << 4) + q * 4;
            unsigned hw = *(const unsigned*)(sm + hpb + bo);
            unsigned lw = *(const unsigned*)(sm + hpb + 12800 + bo);
            float h0 = blo(hw) + blo(lw), h1 = bhi(hw) + bhi(lw);
            float z0 = sigf(C[nt * 4 + 2] + bi.x + bh2.x);
            float z1 = sigf(C[nt * 4 + 3] + bi.y + bh2.y);
            float n0 = rg[nt * 4 + 2], n1 = rg[nt * 4 + 3];
            float2 o;
            o.x = fmaf(z0, h0 - n0, n0);
            o.y = fmaf(z1, h1 - n1, n1);
            *(float2*)(hdst + (g * NPG + half * 100 + r2l) * 64 + col) = o;
        }
    }
#undef STAGEW
#undef MMPASS
}

// ---------------- batched LSTM: 40 CTAs x 8 graphs ----------------
__global__ __launch_bounds__(256) void lstm_kernel() {
    __shared__ float xs[8][128];
    __shared__ float hp[8][64];
    __shared__ float cp[8][64];
    __shared__ float gs[8][256];
    const int tid = threadIdx.x;
    const int g0 = blockIdx.x * 8;
    for (int i = tid; i < 1024; i += 256) {
        int j = i >> 7, k = i & 127;
        xs[j][k] = g_qstar[(g0 + j) * 128 + k];
    }
    const int ihbase[3] = { 0, 49152, 81920 };
    const int hhbase[3] = { 32768, 65536, 98304 };
    for (int l = 0; l < 3; l++) {
        int nk4 = l ? 16 : 32;
        for (int i = tid; i < 512; i += 256) {
            int j = i >> 6, d = i & 63;
            hp[j][d] = g_lh[l * NGR * 64 + (g0 + j) * 64 + d];
            cp[j][d] = g_lc[l * NGR * 64 + (g0 + j) * 64 + d];
        }
        __syncthreads();
        float acc[8];
        float bs = g_bsum[l * 256 + tid];
#pragma unroll
        for (int j = 0; j < 8; j++) acc[j] = bs;
        const float4* Wi = (const float4*)(g_wtl + ihbase[l]) + tid;
        for (int k4 = 0; k4 < nk4; k4++) {
            float4 w = Wi[k4 * 256];
#pragma unroll
            for (int j = 0; j < 8; j++) {
                float4 xv = *(const float4*)&xs[j][k4 * 4];
                acc[j] = fmaf(w.x, xv.x, fmaf(w.y, xv.y, fmaf(w.z, xv.z, fmaf(w.w, xv.w, acc[j]))));
            }
        }
        const float4* Wh = (const float4*)(g_wtl + hhbase[l]) + tid;
        for (int k4 = 0; k4 < 16; k4++) {
            float4 w = Wh[k4 * 256];
#pragma unroll
            for (int j = 0; j < 8; j++) {
                float4 hv = *(const float4*)&hp[j][k4 * 4];
                acc[j] = fmaf(w.x, hv.x, fmaf(w.y, hv.y, fmaf(w.z, hv.z, fmaf(w.w, hv.w, acc[j]))));
            }
        }
#pragma unroll
        for (int j = 0; j < 8; j++) gs[j][tid] = acc[j];
        __syncthreads();
        for (int i = tid; i < 512; i += 256) {
            int j = i >> 6, d = i & 63;
            float c = sigf(gs[j][64 + d]) * cp[j][d] + sigf(gs[j][d]) * tanhfast(gs[j][128 + d]);
            float hn = sigf(gs[j][192 + d]) * tanhfast(c);
            g_lc[l * NGR * 64 + (g0 + j) * 64 + d] = c;
            g_lh[l * NGR * 64 + (g0 + j) * 64 + d] = hn;
            xs[j][d] = hn;
            if (l == 2) g_q[(g0 + j) * 64 + d] = hn;
        }
        __syncthreads();
    }
}

// ---------------- attention: one CTA per graph ----------------
#define AP 68
#define ATT_SMEM ((13600 + 64 + 64 + 200 + 256) * 4)

__global__ __launch_bounds__(256, 2) void attn_kernel(
    const float* __restrict__ Wp, const float* __restrict__ bp,
    float* __restrict__ out, int last) {
    extern __shared__ float smf[];
    float* hs    = smf;
    float* qv    = smf + 13600;
    float* red   = smf + 13664;
    float* alpha = smf + 13728;
    float* part  = smf + 13928;
    const int tid = threadIdx.x;
    const int g = blockIdx.x;
    const int lane = tid & 31;
    const int wrp = tid >> 5;

    for (int i = tid; i < 3200; i += 256) {
        int n = i >> 4, c4 = i & 15;
        *(float4*)&hs[n * AP + c4 * 4] = *(const float4*)(g_hA + (g * NPG + n) * 64 + c4 * 4);
    }
    if (tid < 64) qv[tid] = g_q[g * 64 + tid];
    __syncthreads();

    float e = -3.4e38f;
    if (tid < NPG) {
        float a = 0.0f;
#pragma unroll 4
        for (int c4 = 0; c4 < 16; c4++) {
            float4 hv = *(const float4*)&hs[tid * AP + c4 * 4];
            float4 q4 = *(const float4*)&qv[c4 * 4];
            a = fmaf(hv.x, q4.x, fmaf(hv.y, q4.y, fmaf(hv.z, q4.z, fmaf(hv.w, q4.w, a))));
        }
        e = a;
    }
    float m = e;
#pragma unroll
    for (int o = 16; o >= 1; o >>= 1) m = fmaxf(m, __shfl_xor_sync(0xffffffffu, m, o));
    if (lane == 0) red[wrp] = m;
    __syncthreads();
    if (tid == 0) {
        float mm = red[0];
        for (int w = 1; w < 8; w++) mm = fmaxf(mm, red[w]);
        red[32] = mm;
    }
    __syncthreads();
    float ex = (tid < NPG) ? __expf(e - red[32]) : 0.0f;
    float ss = ex;
#pragma unroll
    for (int o = 16; o >= 1; o >>= 1) ss += __shfl_xor_sync(0xffffffffu, ss, o);
    if (lane == 0) red[wrp] = ss;
    __syncthreads();
    if (tid == 0) {
        float s = 0.0f;
        for (int w = 0; w < 8; w++) s += red[w];
        red[33] = s;
    }
    __syncthreads();
    if (tid < NPG) alpha[tid] = ex / red[33];
    __syncthreads();
    {
        int d = tid & 63, grp = tid >> 6;
        float a = 0.0f;
        int nlo = grp * 50;
        for (int n = nlo; n < nlo + 50; n++)
            a = fmaf(hs[n * AP + d], alpha[n], a);
        part[tid] = a;
    }
    __syncthreads();
    if (tid < 64) {
        float ro = part[tid] + part[64 + tid] + part[128 + tid] + part[192 + tid];
        g_qstar[g * 128 + tid] = qv[tid];
        g_qstar[g * 128 + 64 + tid] = ro;
    }
    if (last) {
        __syncthreads();
        if (tid < 3) {
            float a = bp[tid];
            for (int j = 0; j < 128; j++)
                a = fmaf(g_qstar[g * 128 + j], Wp[tid * 128 + j], a);
            out[g * 3 + tid] = a;
        }
    }
}

extern "C" void kernel_launch(void* const* d_in, const int* in_sizes, int n_in,
                              void* d_out, int out_size) {
    const float* feats  = (const float*)d_in[0];
    const float* W_edge = (const float*)d_in[1];
    const float* b_edge = (const float*)d_in[2];
    const float* gWih   = (const float*)d_in[3];
    const float* gWhh   = (const float*)d_in[4];
    const float* gbih   = (const float*)d_in[5];
    const float* gbhh   = (const float*)d_in[6];
    const float* wih0 = (const float*)d_in[7];
    const float* whh0 = (const float*)d_in[8];
    const float* bih0 = (const float*)d_in[9];
    const float* bhh0 = (const float*)d_in[10];
    const float* wih1 = (const float*)d_in[11];
    const float* whh1 = (const float*)d_in[12];
    const float* bih1 = (const float*)d_in[13];
    const float* bhh1 = (const float*)d_in[14];
    const float* wih2 = (const float*)d_in[15];
    const float* whh2 = (const float*)d_in[16];
    const float* bih2 = (const float*)d_in[17];
    const float* bhh2 = (const float*)d_in[18];
    const float* Wp   = (const float*)d_in[19];
    const float* bp   = (const float*)d_in[20];
    const int* src    = (const int*)d_in[21];
    const int* dst    = (const int*)d_in[22];
    const int* ety    = (const int*)d_in[23];
    float* out = (float*)d_out;

    static int inited = 0;
    if (!inited) {
        cudaFuncSetAttribute(step_kernel,
                             cudaFuncAttributeMaxDynamicSharedMemorySize, ST_SMEM);
        cudaFuncSetAttribute(attn_kernel,
                             cudaFuncAttributeMaxDynamicSharedMemorySize, ATT_SMEM);
        inited = 1;
    }

    prep_kernel<<<192, 256>>>(W_edge, gWih, gWhh);
    prep_lstm<<<452, 256>>>(wih0, whh0, bih0, bhh0,
                            wih1, whh1, bih1, bhh1,
                            wih2, whh2, bih2, bhh2);
    sort_kernel<<<NGR, 640>>>(src, dst, ety);
    for (int s = 0; s < 5; s++)
        step_kernel<<<NGR * 2, NTH, ST_SMEM>>>(feats, b_edge, gbih, gbhh, s);
    for (int it = 0; it < 6; it++) {
        lstm_kernel<<<40, 256>>>();
        attn_kernel<<<NGR, 256, ATT_SMEM>>>(Wp, bp, out, it == 5 ? 1 : 0);
    }
}